// round 10
// baseline (speedup 1.0000x reference)
#include <cuda_runtime.h>
#include <math.h>

// Problem constants
#define N_IMG 4
#define C_DIM 256
#define H_DIM 50
#define W_DIM 50
#define HW (H_DIM * W_DIM)
#define PH 7
#define PW 7
#define NBINS (PH * PW)
#define N_ROI 1024
#define OUT_PER_ROI (C_DIM * NBINS)   // 12544 floats
#define SPATIAL_SCALE 0.0625f
#define ROW_STRIDE (W_DIM * C_DIM)    // floats per h-row in NHWC

// fl(1/7) in fp32 — XLA rewrites (x / 7) into (x * fl(1/7)); we must match it.
#define RCP_7 0.14285714924335479736328125f

// Scratch: x transposed to [N][H][W][C] (channels-last) = 10.24 MB
__device__ float g_xt[N_IMG * HW * C_DIM];

// Precomputed per-roi geometry (ints, computed once with exact XLA numerics)
__device__ int g_boff[N_ROI];        // image base offset in floats
__device__ int g_hs[N_ROI * PH];
__device__ int g_he[N_ROI * PH];
__device__ int g_ws[N_ROI * PW];
__device__ int g_we[N_ROI * PW];

// ---------------------------------------------------------------------------
// Vectorized transpose NCHW -> NHWC. 32(hw) x 32(c) tiles, float4 on both
// the load (along hw; HW=2500 is divisible by 4) and the store (along c).
// Block = (8, 32) = 256 threads. Conflict-free smem via [33] padding.
// Block (0,0,0) additionally precomputes all roi bin edges (256 threads x
// 4 rois) — zero extra launch, exact XLA numerics isolated here.
// ---------------------------------------------------------------------------
__global__ void __launch_bounds__(256) transpose_kernel(const float* __restrict__ x,
                                                        const float* __restrict__ rois) {
    __shared__ float tile[32][33];   // [hw_local][c_local]

    if (blockIdx.x == 0 && blockIdx.y == 0 && blockIdx.z == 0) {
        const int tid = threadIdx.y * 8 + threadIdx.x;
        #pragma unroll
        for (int q = 0; q < 4; ++q) {
            const int roi = tid * 4 + q;   // 0..1023
            const float* r = rois + roi * 5;
            const int b  = (int)r[0];
            const int xs = (int)rintf(__fmul_rn(r[1], SPATIAL_SCALE));
            const int ys = (int)rintf(__fmul_rn(r[2], SPATIAL_SCALE));
            const int xe = (int)rintf(__fmul_rn(r[3], SPATIAL_SCALE));
            const int ye = (int)rintf(__fmul_rn(r[4], SPATIAL_SCALE));
            const float rw = (float)max(xe - xs + 1, 1);
            const float rh = (float)max(ye - ys + 1, 1);
            const float bh = __fmul_rn(rh, RCP_7);   // XLA reciprocal-multiply
            const float bw = __fmul_rn(rw, RCP_7);

            g_boff[roi] = b * (HW * C_DIM);
            #pragma unroll
            for (int p = 0; p < PH; ++p) {
                int hs = (int)floorf(__fmul_rn((float)p,        bh)) + ys;
                int he = (int)ceilf (__fmul_rn((float)p + 1.0f, bh)) + ys;
                int ws = (int)floorf(__fmul_rn((float)p,        bw)) + xs;
                int we = (int)ceilf (__fmul_rn((float)p + 1.0f, bw)) + xs;
                g_hs[roi * PH + p] = min(max(hs, 0), H_DIM);
                g_he[roi * PH + p] = min(max(he, 0), H_DIM);
                g_ws[roi * PW + p] = min(max(ws, 0), W_DIM);
                g_we[roi * PW + p] = min(max(we, 0), W_DIM);
            }
        }
    }

    const int n   = blockIdx.z;
    const int hw0 = blockIdx.x * 32;
    const int c0b = blockIdx.y * 32;

    // Load: float4 along hw. thread (tx in [0,8), ty in [0,32)):
    //   c = c0b + ty, hw = hw0 + tx*4 .. +3
    {
        const int c  = c0b + threadIdx.y;
        const int hw = hw0 + threadIdx.x * 4;
        if (hw + 3 < HW) {
            const float4 v = *(const float4*)&x[(n * C_DIM + c) * HW + hw];
            const int hl = threadIdx.x * 4;
            tile[hl + 0][threadIdx.y] = v.x;
            tile[hl + 1][threadIdx.y] = v.y;
            tile[hl + 2][threadIdx.y] = v.z;
            tile[hl + 3][threadIdx.y] = v.w;
        }
    }
    __syncthreads();

    // Store: float4 along c. thread: hw = hw0 + ty, c = c0b + tx*4 .. +3
    {
        const int hw = hw0 + threadIdx.y;
        if (hw < HW) {
            const int cl = threadIdx.x * 4;
            float4 v;
            v.x = tile[threadIdx.y][cl + 0];
            v.y = tile[threadIdx.y][cl + 1];
            v.z = tile[threadIdx.y][cl + 2];
            v.w = tile[threadIdx.y][cl + 3];
            *(float4*)&g_xt[(size_t)(n * HW + hw) * C_DIM + c0b + cl] = v;
        }
    }
}

// ---------------------------------------------------------------------------
// RoI max pooling: one block per (roi, ph-row). Grid = 1024 x 7.
// Block = 256 threads = 4 pw-groups x 64 lanes (float4 -> 256 channels).
// Each pw-group handles pw = grp, then pw = grp + 4.
//
// Hot loop: branch-free clamped 2x2 body. h+1 clamps to he-1, w+1 clamps to
// we-1 — duplicated loads are identities under max, so there is NO remainder
// code: every trip issues 4 independent LDG.128 (steady MLP) with only
// 2 IMNMX + loop bookkeeping of overhead.
// ---------------------------------------------------------------------------
__global__ void __launch_bounds__(256, 6) roipool_kernel(float* __restrict__ out) {
    __shared__ float s_out[C_DIM * PW];   // [c][pw] = 7168 B

    const int roi = blockIdx.x;
    const int ph  = blockIdx.y;

    const int boff = __ldg(&g_boff[roi]);
    const int hs   = __ldg(&g_hs[roi * PH + ph]);
    const int he   = __ldg(&g_he[roi * PH + ph]);

    const int lane = threadIdx.x & 63;   // 64 lanes -> 256 channels via float4
    const int grp  = threadIdx.x >> 6;   // 4 pw-groups
    const int c0   = lane * 4;

    const float* __restrict__ base = g_xt + boff + c0;

    #pragma unroll 1
    for (int it = 0; it < 2; ++it) {
        const int pw = it * 4 + grp;
        if (pw < PW) {
            const int ws = __ldg(&g_ws[roi * PW + pw]);
            const int we = __ldg(&g_we[roi * PW + pw]);

            float m0 = -INFINITY, m1 = -INFINITY, m2 = -INFINITY, m3 = -INFINITY;

            if (hs < he && ws < we) {
                #pragma unroll 1
                for (int h = hs; h < he; h += 2) {
                    const int h1 = min(h + 1, he - 1);          // clamp: dup row OK
                    const float* p0 = base + h  * ROW_STRIDE;
                    const float* p1 = base + h1 * ROW_STRIDE;
                    #pragma unroll 1
                    for (int w = ws; w < we; w += 2) {
                        const int w1 = min(w + 1, we - 1);      // clamp: dup col OK
                        const float4 va = *(const float4*)(p0 + w  * C_DIM);
                        const float4 vb = *(const float4*)(p0 + w1 * C_DIM);
                        const float4 vc = *(const float4*)(p1 + w  * C_DIM);
                        const float4 vd = *(const float4*)(p1 + w1 * C_DIM);
                        m0 = fmaxf(fmaxf(fmaxf(m0, va.x), vb.x), fmaxf(vc.x, vd.x));
                        m1 = fmaxf(fmaxf(fmaxf(m1, va.y), vb.y), fmaxf(vc.y, vd.y));
                        m2 = fmaxf(fmaxf(fmaxf(m2, va.z), vb.z), fmaxf(vc.z, vd.z));
                        m3 = fmaxf(fmaxf(fmaxf(m3, va.w), vb.w), fmaxf(vc.w, vd.w));
                    }
                }
            } else {
                m0 = m1 = m2 = m3 = 0.0f;                       // empty bin -> 0
            }

            s_out[(c0 + 0) * PW + pw] = m0;
            s_out[(c0 + 1) * PW + pw] = m1;
            s_out[(c0 + 2) * PW + pw] = m2;
            s_out[(c0 + 3) * PW + pw] = m3;
        }
    }
    __syncthreads();

    // Store: out[roi, c, ph, pw] = s_out[c*7 + pw].
    float* __restrict__ obase = out + (size_t)roi * OUT_PER_ROI + ph * PW;
    #pragma unroll 1
    for (int i = threadIdx.x; i < C_DIM * PW; i += 256) {
        const int c  = i / PW;
        const int pw = i - c * PW;
        obase[c * NBINS + pw] = s_out[i];
    }
}

extern "C" void kernel_launch(void* const* d_in, const int* in_sizes, int n_in,
                              void* d_out, int out_size) {
    const float* x    = (const float*)d_in[0];
    const float* rois = (const float*)d_in[1];
    float* out        = (float*)d_out;

    (void)in_sizes; (void)n_in; (void)out_size;

    dim3 tgrid((HW + 127) / 128 * 4, C_DIM / 32, N_IMG);   // 32 hw per tile.x
    // grid.x must cover HW in 32-hw tiles: (2500+31)/32 = 79
    dim3 tgrid_fixed(79, C_DIM / 32, N_IMG);
    dim3 tblk(8, 32);
    transpose_kernel<<<tgrid_fixed, tblk>>>(x, rois);

    dim3 pgrid(N_ROI, PH);
    roipool_kernel<<<pgrid, 256>>>(out);
}

// round 11
// speedup vs baseline: 1.0216x; 1.0216x over previous
#include <cuda_runtime.h>
#include <math.h>

// Problem constants
#define N_IMG 4
#define C_DIM 256
#define H_DIM 50
#define W_DIM 50
#define HW (H_DIM * W_DIM)
#define PH 7
#define PW 7
#define NBINS (PH * PW)
#define N_ROI 1024
#define OUT_PER_ROI (C_DIM * NBINS)   // 12544 floats
#define SPATIAL_SCALE 0.0625f
#define ROW_STRIDE (W_DIM * C_DIM)    // floats per h-row in NHWC

// fl(1/7) in fp32 — XLA rewrites (x / 7) into (x * fl(1/7)); we must match it.
#define RCP_7 0.14285714924335479736328125f

// Scratch: x transposed to [N][H][W][C] (channels-last) = 10.24 MB
__device__ float g_xt[N_IMG * HW * C_DIM];

// Precomputed per-roi geometry (ints, computed once with exact XLA numerics)
__device__ int g_boff[N_ROI];        // image base offset in floats
__device__ int g_hs[N_ROI * PH];
__device__ int g_he[N_ROI * PH];
__device__ int g_ws[N_ROI * PW];
__device__ int g_we[N_ROI * PW];

// ---------------------------------------------------------------------------
// Transpose NCHW -> NHWC via 32x32 smem tiles (proven-fast scalar version).
// Block (0,0,0) additionally precomputes all roi bin edges (1024 threads =
// 1024 rois) — zero extra launch, exact XLA numerics isolated here.
// ---------------------------------------------------------------------------
__global__ void __launch_bounds__(1024) transpose_kernel(const float* __restrict__ x,
                                                         const float* __restrict__ rois) {
    __shared__ float tile[32][33];

    if (blockIdx.x == 0 && blockIdx.y == 0 && blockIdx.z == 0) {
        const int roi = threadIdx.y * 32 + threadIdx.x;   // 0..1023
        const float* r = rois + roi * 5;
        const int b  = (int)r[0];
        const int xs = (int)rintf(__fmul_rn(r[1], SPATIAL_SCALE));
        const int ys = (int)rintf(__fmul_rn(r[2], SPATIAL_SCALE));
        const int xe = (int)rintf(__fmul_rn(r[3], SPATIAL_SCALE));
        const int ye = (int)rintf(__fmul_rn(r[4], SPATIAL_SCALE));
        const float rw = (float)max(xe - xs + 1, 1);
        const float rh = (float)max(ye - ys + 1, 1);
        const float bh = __fmul_rn(rh, RCP_7);   // XLA reciprocal-multiply
        const float bw = __fmul_rn(rw, RCP_7);

        g_boff[roi] = b * (HW * C_DIM);
        #pragma unroll
        for (int p = 0; p < PH; ++p) {
            int hs = (int)floorf(__fmul_rn((float)p,        bh)) + ys;
            int he = (int)ceilf (__fmul_rn((float)p + 1.0f, bh)) + ys;
            int ws = (int)floorf(__fmul_rn((float)p,        bw)) + xs;
            int we = (int)ceilf (__fmul_rn((float)p + 1.0f, bw)) + xs;
            g_hs[roi * PH + p] = min(max(hs, 0), H_DIM);
            g_he[roi * PH + p] = min(max(he, 0), H_DIM);
            g_ws[roi * PW + p] = min(max(ws, 0), W_DIM);
            g_we[roi * PW + p] = min(max(we, 0), W_DIM);
        }
    }

    const int n   = blockIdx.z;
    const int hw0 = blockIdx.x * 32;
    const int c0b = blockIdx.y * 32;
    {
        const int c  = c0b + threadIdx.y;
        const int hw = hw0 + threadIdx.x;
        if (hw < HW) {
            tile[threadIdx.y][threadIdx.x] = x[(n * C_DIM + c) * HW + hw];
        }
    }
    __syncthreads();
    {
        const int hw = hw0 + threadIdx.y;
        const int c  = c0b + threadIdx.x;
        if (hw < HW) {
            g_xt[(n * HW + hw) * C_DIM + c] = tile[threadIdx.x][threadIdx.y];
        }
    }
}

// ---------------------------------------------------------------------------
// RoI max pooling: one block per (roi, ph-row). Grid = 1024 x 7.
// Block = 256 threads = 4 pw-groups x 64 lanes (float4 -> 256 channels).
// Each pw-group handles pw = grp, then pw = grp + 4.
// Hot loop is the exact 2x2 (h,w) diamond (R9): FOUR independent LDG.128
// in flight per main-body iteration, exact remainders (no duplicate loads).
// __launch_bounds__(256, 7): cap regs at 36 -> 7 CTAs/SM = 56 warps (87%).
// ---------------------------------------------------------------------------
__global__ void __launch_bounds__(256, 7) roipool_kernel(float* __restrict__ out) {
    __shared__ float s_out[C_DIM * PW];   // [c][pw] = 7168 B

    const int roi = blockIdx.x;
    const int ph  = blockIdx.y;

    const int boff = __ldg(&g_boff[roi]);
    const int hs   = __ldg(&g_hs[roi * PH + ph]);
    const int he   = __ldg(&g_he[roi * PH + ph]);

    const int lane = threadIdx.x & 63;   // 64 lanes -> 256 channels via float4
    const int grp  = threadIdx.x >> 6;   // 4 pw-groups
    const int c0   = lane * 4;

    const float* __restrict__ base = g_xt + boff + c0;

    #pragma unroll 1
    for (int it = 0; it < 2; ++it) {
        const int pw = it * 4 + grp;
        if (pw < PW) {
            const int ws = __ldg(&g_ws[roi * PW + pw]);
            const int we = __ldg(&g_we[roi * PW + pw]);

            float m0 = -INFINITY, m1 = -INFINITY, m2 = -INFINITY, m3 = -INFINITY;
            const bool empty = (hs >= he) || (ws >= we);

            int h = hs;
            #pragma unroll 1
            for (; h + 1 < he; h += 2) {           // two rows per trip
                const float* p0 = base + h * ROW_STRIDE;
                const float* p1 = p0 + ROW_STRIDE;
                int w = ws;
                #pragma unroll 1
                for (; w + 1 < we; w += 2) {       // 2x2 diamond: 4 loads in flight
                    const float4 va = *(const float4*)(p0 + w * C_DIM);
                    const float4 vb = *(const float4*)(p0 + (w + 1) * C_DIM);
                    const float4 vc = *(const float4*)(p1 + w * C_DIM);
                    const float4 vd = *(const float4*)(p1 + (w + 1) * C_DIM);
                    m0 = fmaxf(fmaxf(fmaxf(m0, va.x), vb.x), fmaxf(vc.x, vd.x));
                    m1 = fmaxf(fmaxf(fmaxf(m1, va.y), vb.y), fmaxf(vc.y, vd.y));
                    m2 = fmaxf(fmaxf(fmaxf(m2, va.z), vb.z), fmaxf(vc.z, vd.z));
                    m3 = fmaxf(fmaxf(fmaxf(m3, va.w), vb.w), fmaxf(vc.w, vd.w));
                }
                if (w < we) {                      // odd-width remainder: 2 loads
                    const float4 va = *(const float4*)(p0 + w * C_DIM);
                    const float4 vc = *(const float4*)(p1 + w * C_DIM);
                    m0 = fmaxf(m0, fmaxf(va.x, vc.x));
                    m1 = fmaxf(m1, fmaxf(va.y, vc.y));
                    m2 = fmaxf(m2, fmaxf(va.z, vc.z));
                    m3 = fmaxf(m3, fmaxf(va.w, vc.w));
                }
            }
            if (h < he) {                          // odd-height remainder row
                const float* p0 = base + h * ROW_STRIDE;
                int w = ws;
                #pragma unroll 1
                for (; w + 1 < we; w += 2) {
                    const float4 va = *(const float4*)(p0 + w * C_DIM);
                    const float4 vb = *(const float4*)(p0 + (w + 1) * C_DIM);
                    m0 = fmaxf(m0, fmaxf(va.x, vb.x));
                    m1 = fmaxf(m1, fmaxf(va.y, vb.y));
                    m2 = fmaxf(m2, fmaxf(va.z, vb.z));
                    m3 = fmaxf(m3, fmaxf(va.w, vb.w));
                }
                if (w < we) {
                    const float4 va = *(const float4*)(p0 + w * C_DIM);
                    m0 = fmaxf(m0, va.x); m1 = fmaxf(m1, va.y);
                    m2 = fmaxf(m2, va.z); m3 = fmaxf(m3, va.w);
                }
            }
            if (empty) { m0 = m1 = m2 = m3 = 0.0f; }

            s_out[(c0 + 0) * PW + pw] = m0;
            s_out[(c0 + 1) * PW + pw] = m1;
            s_out[(c0 + 2) * PW + pw] = m2;
            s_out[(c0 + 3) * PW + pw] = m3;
        }
    }
    __syncthreads();

    // Store: out[roi, c, ph, pw] = s_out[c*7 + pw].
    float* __restrict__ obase = out + (size_t)roi * OUT_PER_ROI + ph * PW;
    #pragma unroll 1
    for (int i = threadIdx.x; i < C_DIM * PW; i += 256) {
        const int c  = i / PW;
        const int pw = i - c * PW;
        obase[c * NBINS + pw] = s_out[i];
    }
}

extern "C" void kernel_launch(void* const* d_in, const int* in_sizes, int n_in,
                              void* d_out, int out_size) {
    const float* x    = (const float*)d_in[0];
    const float* rois = (const float*)d_in[1];
    float* out        = (float*)d_out;

    (void)in_sizes; (void)n_in; (void)out_size;

    dim3 tgrid((HW + 31) / 32, C_DIM / 32, N_IMG);
    dim3 tblk(32, 32);
    transpose_kernel<<<tgrid, tblk>>>(x, rois);

    dim3 pgrid(N_ROI, PH);
    roipool_kernel<<<pgrid, 256>>>(out);
}

// round 12
// speedup vs baseline: 1.1850x; 1.1600x over previous
#include <cuda_runtime.h>
#include <math.h>

// Problem constants
#define N_IMG 4
#define C_DIM 256
#define H_DIM 50
#define W_DIM 50
#define HW (H_DIM * W_DIM)
#define PH 7
#define PW 7
#define NBINS (PH * PW)
#define N_ROI 1024
#define OUT_PER_ROI (C_DIM * NBINS)   // 12544 floats
#define SPATIAL_SCALE 0.0625f
#define ROW_STRIDE (W_DIM * C_DIM)    // floats per h-row in NHWC

// fl(1/7) in fp32 — XLA rewrites (x / 7) into (x * fl(1/7)); we must match it.
#define RCP_7 0.14285714924335479736328125f

// Scratch: x transposed to [N][H][W][C] (channels-last) = 10.24 MB
__device__ float g_xt[N_IMG * HW * C_DIM];

// Precomputed per-roi geometry. Bounds packed as int2 (one LDG.64 per pair).
__device__ int  g_boff[N_ROI];        // image base offset in floats
__device__ int2 g_hse[N_ROI * PH];    // (hs, he)
__device__ int2 g_wse[N_ROI * PW];    // (ws, we)

// ---------------------------------------------------------------------------
// Transpose NCHW -> NHWC via 32x32 smem tiles (proven-fast scalar version).
// Block (0,0,0) additionally precomputes all roi bin edges (1024 threads =
// 1024 rois) — zero extra launch, exact XLA numerics isolated here.
// ---------------------------------------------------------------------------
__global__ void __launch_bounds__(1024) transpose_kernel(const float* __restrict__ x,
                                                         const float* __restrict__ rois) {
    __shared__ float tile[32][33];

    if (blockIdx.x == 0 && blockIdx.y == 0 && blockIdx.z == 0) {
        const int roi = threadIdx.y * 32 + threadIdx.x;   // 0..1023
        const float* r = rois + roi * 5;
        const int b  = (int)r[0];
        const int xs = (int)rintf(__fmul_rn(r[1], SPATIAL_SCALE));
        const int ys = (int)rintf(__fmul_rn(r[2], SPATIAL_SCALE));
        const int xe = (int)rintf(__fmul_rn(r[3], SPATIAL_SCALE));
        const int ye = (int)rintf(__fmul_rn(r[4], SPATIAL_SCALE));
        const float rw = (float)max(xe - xs + 1, 1);
        const float rh = (float)max(ye - ys + 1, 1);
        const float bh = __fmul_rn(rh, RCP_7);   // XLA reciprocal-multiply
        const float bw = __fmul_rn(rw, RCP_7);

        g_boff[roi] = b * (HW * C_DIM);
        #pragma unroll
        for (int p = 0; p < PH; ++p) {
            int hs = (int)floorf(__fmul_rn((float)p,        bh)) + ys;
            int he = (int)ceilf (__fmul_rn((float)p + 1.0f, bh)) + ys;
            int ws = (int)floorf(__fmul_rn((float)p,        bw)) + xs;
            int we = (int)ceilf (__fmul_rn((float)p + 1.0f, bw)) + xs;
            g_hse[roi * PH + p] = make_int2(min(max(hs, 0), H_DIM),
                                            min(max(he, 0), H_DIM));
            g_wse[roi * PW + p] = make_int2(min(max(ws, 0), W_DIM),
                                            min(max(we, 0), W_DIM));
        }
    }

    const int n   = blockIdx.z;
    const int hw0 = blockIdx.x * 32;
    const int c0b = blockIdx.y * 32;
    {
        const int c  = c0b + threadIdx.y;
        const int hw = hw0 + threadIdx.x;
        if (hw < HW) {
            tile[threadIdx.y][threadIdx.x] = x[(n * C_DIM + c) * HW + hw];
        }
    }
    __syncthreads();
    {
        const int hw = hw0 + threadIdx.y;
        const int c  = c0b + threadIdx.x;
        if (hw < HW) {
            g_xt[(n * HW + hw) * C_DIM + c] = tile[threadIdx.x][threadIdx.y];
        }
    }
}

// ---------------------------------------------------------------------------
// RoI max pooling: one block per (roi, ph-row). Grid = 1024 x 7.
// Block = 448 threads = 7 pw-groups x 64 lanes (float4 -> 256 channels).
// ONE bin per thread — no outer bin loop, no guard, one packed bound load.
// Hot loop is the exact 2x2 (h,w) diamond (R9): FOUR independent LDG.128
// in flight per main-body iteration, exact remainders (no duplicate loads).
// __launch_bounds__(448, 3): 48-reg budget (diamond needs ~40, no
// serialization), 3 CTAs/SM = 42 warps.
// ---------------------------------------------------------------------------
__global__ void __launch_bounds__(448, 3) roipool_kernel(float* __restrict__ out) {
    __shared__ float s_out[C_DIM * PW];   // [c][pw] = 7168 B

    const int roi = blockIdx.x;
    const int ph  = blockIdx.y;

    const int  boff = __ldg(&g_boff[roi]);
    const int2 hse  = __ldg(&g_hse[roi * PH + ph]);
    const int  hs = hse.x, he = hse.y;

    const int lane = threadIdx.x & 63;   // 64 lanes -> 256 channels via float4
    const int pw   = threadIdx.x >> 6;   // 7 pw-groups = 7 bins
    const int c0   = lane * 4;

    const int2 wse = __ldg(&g_wse[roi * PW + pw]);
    const int  ws = wse.x, we = wse.y;

    const float* __restrict__ base = g_xt + boff + c0;

    float m0 = -INFINITY, m1 = -INFINITY, m2 = -INFINITY, m3 = -INFINITY;
    const bool empty = (hs >= he) || (ws >= we);

    int h = hs;
    #pragma unroll 1
    for (; h + 1 < he; h += 2) {           // two rows per trip
        const float* p0 = base + h * ROW_STRIDE;
        const float* p1 = p0 + ROW_STRIDE;
        int w = ws;
        #pragma unroll 1
        for (; w + 1 < we; w += 2) {       // 2x2 diamond: 4 loads in flight
            const float4 va = *(const float4*)(p0 + w * C_DIM);
            const float4 vb = *(const float4*)(p0 + (w + 1) * C_DIM);
            const float4 vc = *(const float4*)(p1 + w * C_DIM);
            const float4 vd = *(const float4*)(p1 + (w + 1) * C_DIM);
            m0 = fmaxf(fmaxf(fmaxf(m0, va.x), vb.x), fmaxf(vc.x, vd.x));
            m1 = fmaxf(fmaxf(fmaxf(m1, va.y), vb.y), fmaxf(vc.y, vd.y));
            m2 = fmaxf(fmaxf(fmaxf(m2, va.z), vb.z), fmaxf(vc.z, vd.z));
            m3 = fmaxf(fmaxf(fmaxf(m3, va.w), vb.w), fmaxf(vc.w, vd.w));
        }
        if (w < we) {                      // odd-width remainder: 2 loads
            const float4 va = *(const float4*)(p0 + w * C_DIM);
            const float4 vc = *(const float4*)(p1 + w * C_DIM);
            m0 = fmaxf(m0, fmaxf(va.x, vc.x));
            m1 = fmaxf(m1, fmaxf(va.y, vc.y));
            m2 = fmaxf(m2, fmaxf(va.z, vc.z));
            m3 = fmaxf(m3, fmaxf(va.w, vc.w));
        }
    }
    if (h < he) {                          // odd-height remainder row
        const float* p0 = base + h * ROW_STRIDE;
        int w = ws;
        #pragma unroll 1
        for (; w + 1 < we; w += 2) {
            const float4 va = *(const float4*)(p0 + w * C_DIM);
            const float4 vb = *(const float4*)(p0 + (w + 1) * C_DIM);
            m0 = fmaxf(m0, fmaxf(va.x, vb.x));
            m1 = fmaxf(m1, fmaxf(va.y, vb.y));
            m2 = fmaxf(m2, fmaxf(va.z, vb.z));
            m3 = fmaxf(m3, fmaxf(va.w, vb.w));
        }
        if (w < we) {
            const float4 va = *(const float4*)(p0 + w * C_DIM);
            m0 = fmaxf(m0, va.x); m1 = fmaxf(m1, va.y);
            m2 = fmaxf(m2, va.z); m3 = fmaxf(m3, va.w);
        }
    }
    if (empty) { m0 = m1 = m2 = m3 = 0.0f; }

    s_out[(c0 + 0) * PW + pw] = m0;
    s_out[(c0 + 1) * PW + pw] = m1;
    s_out[(c0 + 2) * PW + pw] = m2;
    s_out[(c0 + 3) * PW + pw] = m3;
    __syncthreads();

    // Store: out[roi, c, ph, pw] = s_out[c*7 + pw]  (1792 floats, 448 thr).
    float* __restrict__ obase = out + (size_t)roi * OUT_PER_ROI + ph * PW;
    #pragma unroll
    for (int i = threadIdx.x; i < C_DIM * PW; i += 448) {
        const int c  = i / PW;
        const int pwi = i - c * PW;
        obase[c * NBINS + pwi] = s_out[i];
    }
}

extern "C" void kernel_launch(void* const* d_in, const int* in_sizes, int n_in,
                              void* d_out, int out_size) {
    const float* x    = (const float*)d_in[0];
    const float* rois = (const float*)d_in[1];
    float* out        = (float*)d_out;

    (void)in_sizes; (void)n_in; (void)out_size;

    dim3 tgrid((HW + 31) / 32, C_DIM / 32, N_IMG);
    dim3 tblk(32, 32);
    transpose_kernel<<<tgrid, tblk>>>(x, rois);

    dim3 pgrid(N_ROI, PH);
    roipool_kernel<<<pgrid, 448>>>(out);
}